// round 16
// baseline (speedup 1.0000x reference)
#include <cuda_runtime.h>

#define EPS     1e-8f
#define PSD_EPS 1e-5f

constexpr int B = 8, C = 8, F = 257, T = 1500;
constexpr int BF  = B * F;                       // 2056
constexpr long long FT  = (long long)F * T;      // 385500
constexpr long long BFT = (long long)B * F * T;  // 3084000
constexpr int T4 = T / 4;                        // 375
constexpr int FT4 = (int)(FT / 4);               // 96375
constexpr int NCH = 32;                          // F-chunks for mask max

// Scratch (no allocations allowed)
__device__ float g_pmax[2][B][NCH][T];
__device__ float g_recip[2][B][T];

// pair p -> (c,d), c<d, canonical pidx order
__device__ constexpr int PCa[28] = {0,0,0,0,0,0,0, 1,1,1,1,1,1, 2,2,2,2,2, 3,3,3,3, 4,4,4, 5,5, 6};
__device__ constexpr int PDa[28] = {1,2,3,4,5,6,7, 2,3,4,5,6,7, 3,4,5,6,7, 4,5,6,7, 5,6,7, 6,7, 7};

// ---------------------------------------------------------------------------
// Kernel 1a: partial max over F-chunk of |mask|, both masks per thread (ILP 2)
// grid = B*NCH = 256 blocks, 384 threads (375 active).
// ---------------------------------------------------------------------------
__global__ void mask_max_part(const float* __restrict__ sm,
                              const float* __restrict__ nm) {
    int blk = blockIdx.x;
    int chunk = blk & (NCH - 1), b = blk >> 5;
    int i = threadIdx.x;
    if (i >= T4) return;
    // F = 257 = 9 + 31*8
    int fs = chunk ? 9 + (chunk - 1) * 8 : 0;
    int fe = fs + (chunk ? 8 : 9);
    const float4* s4 = (const float4*)(sm + (long long)b * FT);
    const float4* n4 = (const float4*)(nm + (long long)b * FT);
    float4 mxs = make_float4(0.f, 0.f, 0.f, 0.f);
    float4 mxn = make_float4(0.f, 0.f, 0.f, 0.f);
    #pragma unroll 3
    for (int f = fs; f < fe; f++) {
        float4 v = s4[(long long)f * T4 + i];
        float4 w = n4[(long long)f * T4 + i];
        mxs.x = fmaxf(mxs.x, fabsf(v.x)); mxn.x = fmaxf(mxn.x, fabsf(w.x));
        mxs.y = fmaxf(mxs.y, fabsf(v.y)); mxn.y = fmaxf(mxn.y, fabsf(w.y));
        mxs.z = fmaxf(mxs.z, fabsf(v.z)); mxn.z = fmaxf(mxn.z, fabsf(w.z));
        mxs.w = fmaxf(mxs.w, fabsf(v.w)); mxn.w = fmaxf(mxn.w, fabsf(w.w));
    }
    ((float4*)g_pmax[0][b][chunk])[i] = mxs;
    ((float4*)g_pmax[1][b][chunk])[i] = mxn;
}

// Kernel 1b: combine NCH partials -> reciprocal. grid = 16 blocks.
__global__ void mask_recip_kernel() {
    int blk = blockIdx.x;
    int b = blk & 7, m = blk >> 3;
    int i = threadIdx.x;
    if (i >= T4) return;
    float4 a = ((float4*)g_pmax[m][b][0])[i];
    #pragma unroll
    for (int c = 1; c < NCH; c++) {
        float4 v = ((float4*)g_pmax[m][b][c])[i];
        a.x = fmaxf(a.x, v.x); a.y = fmaxf(a.y, v.y);
        a.z = fmaxf(a.z, v.z); a.w = fmaxf(a.w, v.w);
    }
    float4 r;
    r.x = 1.0f / (a.x + EPS); r.y = 1.0f / (a.y + EPS);
    r.z = 1.0f / (a.z + EPS); r.w = 1.0f / (a.w + EPS);
    ((float4*)g_recip[m][b])[i] = r;
}

// ---------------------------------------------------------------------------
// Fused kernel. Phase A: warp-partitioned PSD accumulation.
// Warp W owns pairs [7W,7W+7), diagonals {2W,2W+1}, warp 0 owns densities.
// acc layout per thread: [4j..4j+3] = pair j (S.re,S.im,N.re,N.im),
//                        [28..31] = diag (S0,N0,S1,N1), [32..33] = den (W0).
// ---------------------------------------------------------------------------
__device__ __forceinline__ int pidx(int c, int d) {
    return c * 7 - (c * (c - 1)) / 2 + (d - c - 1);
}

template <int W>
__device__ __forceinline__ void accum_t(float* acc, const float* xr,
                                        const float* xi, float msv, float mnv) {
    #pragma unroll
    for (int j = 0; j < 2; j++) {
        int c = 2 * W + j;
        float p = fmaf(xr[c], xr[c], xi[c] * xi[c]);
        acc[28 + 2 * j]     = fmaf(msv, p, acc[28 + 2 * j]);
        acc[28 + 2 * j + 1] = fmaf(mnv, p, acc[28 + 2 * j + 1]);
    }
    #pragma unroll
    for (int j = 0; j < 7; j++) {
        int p = 7 * W + j;
        int c = PCa[p], d = PDa[p];
        float orr = fmaf(xr[c], xr[d], xi[c] * xi[d]);
        float oii = fmaf(xi[c], xr[d], -xr[c] * xi[d]);
        acc[4 * j + 0] = fmaf(msv, orr, acc[4 * j + 0]);
        acc[4 * j + 1] = fmaf(msv, oii, acc[4 * j + 1]);
        acc[4 * j + 2] = fmaf(mnv, orr, acc[4 * j + 2]);
        acc[4 * j + 3] = fmaf(mnv, oii, acc[4 * j + 3]);
    }
    if (W == 0) { acc[32] += msv; acc[33] += mnv; }
}

#define DO_T(COMP)                                                        \
    {                                                                     \
        float xr[8], xi[8];                                               \
        _Pragma("unroll") for (int c = 0; c < 8; c++) {                   \
            xr[c] = xr4[c].COMP; xi[c] = xi4[c].COMP;                     \
        }                                                                 \
        accum_t<W>(acc, xr, xi, msv.COMP, mnv.COMP);                      \
    }

template <int W>
__device__ __forceinline__ void phaseA(
    float* tile, const float4* cr4, const float4* ci4,
    const float4* sm4, const float4* nm4,
    const float4* rs4, const float4* rn4,
    int lane, float* sacc) {
    float acc[34];
    #pragma unroll
    for (int k = 0; k < 34; k++) acc[k] = 0.f;

    #pragma unroll 1
    for (int i = lane; i < T4; i += 32) {
        float4 xr4[8], xi4[8];
        #pragma unroll
        for (int c = 0; c < 8; c++) {
            xr4[c] = cr4[c * FT4 + i];
            xi4[c] = ci4[c * FT4 + i];
        }
        // stage this warp's 4 assigned rows into the smem tile
        #pragma unroll
        for (int k = 0; k < 4; k++) {
            int r = 4 * W + k;
            float4 v = (r < 8) ? xr4[r] : xi4[r - 8];
            ((float4*)(tile + r * T))[i] = v;
        }
        float4 s = sm4[i], n = nm4[i], a = rs4[i], c = rn4[i];
        float4 msv = make_float4(s.x * a.x, s.y * a.y, s.z * a.z, s.w * a.w);
        float4 mnv = make_float4(n.x * c.x, n.y * c.y, n.z * c.z, n.w * c.w);
        DO_T(x) DO_T(y) DO_T(z) DO_T(w)
    }

    // intra-warp reduction (deterministic), lane 0 publishes
    #pragma unroll
    for (int k = 0; k < 34; k++) {
        float v = acc[k];
        v += __shfl_down_sync(0xffffffffu, v, 16);
        v += __shfl_down_sync(0xffffffffu, v, 8);
        v += __shfl_down_sync(0xffffffffu, v, 4);
        v += __shfl_down_sync(0xffffffffu, v, 2);
        v += __shfl_down_sync(0xffffffffu, v, 1);
        acc[k] = v;
    }
    if (lane == 0) {
        #pragma unroll
        for (int j = 0; j < 7; j++) {
            int p = 7 * W + j;
            sacc[8 + 2 * p]  = acc[4 * j + 0];
            sacc[9 + 2 * p]  = acc[4 * j + 1];
            sacc[73 + 2 * p] = acc[4 * j + 2];
            sacc[74 + 2 * p] = acc[4 * j + 3];
        }
        sacc[2 * W]          = acc[28];
        sacc[65 + 2 * W]     = acc[29];
        sacc[2 * W + 1]      = acc[30];
        sacc[65 + 2 * W + 1] = acc[31];
        if (W == 0) { sacc[64] = acc[32]; sacc[129] = acc[33]; }
    }
}

__device__ __forceinline__ void getS(const float* a, float invs,
                                     int r, int c, float& re, float& im) {
    const float IM0 = PSD_EPS + EPS;
    if (r == c)      { re = a[r] * invs;                 im = IM0; }
    else if (r < c)  { int p = pidx(r, c);
                       re = a[8 + 2 * p] * invs;         im = a[9 + 2 * p] * invs + IM0; }
    else             { int p = pidx(c, r);
                       re = a[8 + 2 * p] * invs;         im = -a[9 + 2 * p] * invs + IM0; }
}

constexpr int DYN_SMEM = 16 * T * (int)sizeof(float);   // 96000 B

__global__ __launch_bounds__(128) void mvdr_fused_kernel(
    const float* __restrict__ sm, const float* __restrict__ nm,
    const float* __restrict__ cr, const float* __restrict__ ci,
    float* __restrict__ out) {
    extern __shared__ float tile[];     // rows 0..7 re, rows 8..15 im
    __shared__ float sacc[130];

    int bf = blockIdx.x;
    int b = bf / F, f = bf % F;
    int tid = threadIdx.x;
    int lane = tid & 31, wid = tid >> 5;

    const float4* cr4 = (const float4*)(cr + (long long)b * C * FT + (long long)f * T);
    const float4* ci4 = (const float4*)(ci + (long long)b * C * FT + (long long)f * T);
    const float4* sm4 = (const float4*)(sm + (long long)b * FT + (long long)f * T);
    const float4* nm4 = (const float4*)(nm + (long long)b * FT + (long long)f * T);
    const float4* rs4 = (const float4*)(g_recip[0][b]);
    const float4* rn4 = (const float4*)(g_recip[1][b]);

    // ---- Phase A ----
    switch (wid) {
        case 0: phaseA<0>(tile, cr4, ci4, sm4, nm4, rs4, rn4, lane, sacc); break;
        case 1: phaseA<1>(tile, cr4, ci4, sm4, nm4, rs4, rn4, lane, sacc); break;
        case 2: phaseA<2>(tile, cr4, ci4, sm4, nm4, rs4, rn4, lane, sacc); break;
        default: phaseA<3>(tile, cr4, ci4, sm4, nm4, rs4, rn4, lane, sacc); break;
    }
    __syncthreads();

    // ---- Phase C: entry-parallel solve (threads 0..63) ----
    __shared__ float rowr[8], rowi[8], colr[8], coli[8];
    __shared__ float sur[8], sui[8], strv[2], tsum[2][2];
    __shared__ float swr[8], swi[8];
    const float* aS = &sacc[0];
    const float* aN = &sacc[65];
    const float IM0 = PSD_EPS + EPS;
    int i8 = tid >> 3, j8 = tid & 7;
    float nr = 0.f, ni = 0.f;

    if (tid < 64) {
        float invd = 1.0f / fmaxf(aN[64], PSD_EPS);
        if (i8 == j8)      { nr = aN[i8] * invd + EPS;  ni = IM0; }
        else if (i8 < j8)  { int p = pidx(i8, j8);
                             nr = aN[8 + 2 * p] * invd; ni = aN[9 + 2 * p] * invd + IM0; }
        else               { int p = pidx(j8, i8);
                             nr = aN[8 + 2 * p] * invd; ni = -aN[9 + 2 * p] * invd + IM0; }
    }

    // Gauss-Jordan, no pivoting (matrix is strongly diagonally dominant)
    #pragma unroll
    for (int k = 0; k < 8; k++) {
        if (tid < 64) {
            if (i8 == k) { rowr[j8] = nr; rowi[j8] = ni; }
            if (j8 == k) { colr[i8] = nr; coli[i8] = ni; }
        }
        __syncthreads();
        if (tid < 64) {
            float pr = rowr[k], pi = rowi[k];
            float s = 1.0f / fmaf(pr, pr, pi * pi);
            float qr = pr * s, qi = -pi * s;
            if (i8 == k) {
                if (j8 == k) { nr = qr; ni = qi; }
                else { float ar = nr, ai = ni;
                       nr = ar * qr - ai * qi; ni = ar * qi + ai * qr; }
            } else {
                float fr = colr[i8], fi = coli[i8];
                float gr = fr * qr - fi * qi, gi = fr * qi + fi * qr;
                if (j8 == k) { nr = -gr; ni = -gi; }
                else {
                    float br = rowr[j8], bi = rowi[j8];
                    nr -= gr * br - gi * bi;
                    ni -= gr * bi + gi * br;
                }
            }
        }
        __syncthreads();
    }

    if (tid < 64) {
        ni += EPS;
        float invs = 1.0f / fmaxf(aS[64], PSD_EPS);
        float sr, si;
        getS(aS, invs, j8, i8, sr, si);
        float tre = nr * sr - ni * si, tim = nr * si + ni * sr;
        getS(aS, invs, j8, 0, sr, si);
        float ue = nr * sr - ni * si, uim = nr * si + ni * sr;
        #pragma unroll
        for (int o = 1; o < 8; o <<= 1) {
            ue  += __shfl_xor_sync(0xffffffffu, ue, o);
            uim += __shfl_xor_sync(0xffffffffu, uim, o);
        }
        if (j8 == 0) { sur[i8] = ue; sui[i8] = uim; }
        #pragma unroll
        for (int o = 16; o >= 1; o >>= 1) {
            tre += __shfl_down_sync(0xffffffffu, tre, o);
            tim += __shfl_down_sync(0xffffffffu, tim, o);
        }
        if (lane == 0) { tsum[wid][0] = tre; tsum[wid][1] = tim; }
    }
    __syncthreads();
    if (tid == 0) {
        strv[0] = EPS + tsum[0][0] + tsum[1][0];
        strv[1] = tsum[0][1] + tsum[1][1];
    }
    __syncthreads();
    if (tid < 8) {
        float trr = strv[0], tri = strv[1];
        float tm = 1.0f / fmaf(trr, trr, tri * tri);
        float ur = sur[tid], ui = sui[tid];
        float wr = (ur * trr + ui * tri) * tm;
        float wi = (ui * trr - ur * tri) * tm;
        swr[tid] = wr;
        swi[tid] = -wi;                           // conj(weight)
    }
    __syncthreads();

    // ---- Phase D: beamform from smem tile, float4 along t ----
    float wr[8], wi[8];
    #pragma unroll
    for (int c = 0; c < 8; c++) { wr[c] = swr[c]; wi[c] = swi[c]; }
    float4* outr = (float4*)(out + (long long)bf * T);
    float4* outi = (float4*)(out + BFT + (long long)bf * T);
    for (int i = tid; i < T4; i += 128) {
        float4 orv = make_float4(0.f, 0.f, 0.f, 0.f);
        float4 oiv = make_float4(0.f, 0.f, 0.f, 0.f);
        #pragma unroll
        for (int c = 0; c < 8; c++) {
            float4 xr = ((const float4*)(tile + c * T))[i];
            float4 xi = ((const float4*)(tile + (8 + c) * T))[i];
            orv.x = fmaf(wr[c], xr.x, fmaf(-wi[c], xi.x, orv.x));
            orv.y = fmaf(wr[c], xr.y, fmaf(-wi[c], xi.y, orv.y));
            orv.z = fmaf(wr[c], xr.z, fmaf(-wi[c], xi.z, orv.z));
            orv.w = fmaf(wr[c], xr.w, fmaf(-wi[c], xi.w, orv.w));
            oiv.x = fmaf(wr[c], xi.x, fmaf(wi[c], xr.x, oiv.x));
            oiv.y = fmaf(wr[c], xi.y, fmaf(wi[c], xr.y, oiv.y));
            oiv.z = fmaf(wr[c], xi.z, fmaf(wi[c], xr.z, oiv.z));
            oiv.w = fmaf(wr[c], xi.w, fmaf(wi[c], xr.w, oiv.w));
        }
        outr[i] = orv;
        outi[i] = oiv;
    }
}

// ---------------------------------------------------------------------------
extern "C" void kernel_launch(void* const* d_in, const int* in_sizes, int n_in,
                              void* d_out, int out_size) {
    const float* sm = (const float*)d_in[0];
    const float* nm = (const float*)d_in[1];
    const float* cr = (const float*)d_in[2];
    const float* ci = (const float*)d_in[3];
    float* out = (float*)d_out;

    cudaFuncSetAttribute(mvdr_fused_kernel,
                         cudaFuncAttributeMaxDynamicSharedMemorySize, DYN_SMEM);

    mask_max_part<<<B * NCH, 384>>>(sm, nm);
    mask_recip_kernel<<<16, 384>>>();
    mvdr_fused_kernel<<<BF, 128, DYN_SMEM>>>(sm, nm, cr, ci, out);
}

// round 17
// speedup vs baseline: 1.5029x; 1.5029x over previous
#include <cuda_runtime.h>

#define EPS     1e-8f
#define PSD_EPS 1e-5f

constexpr int B = 8, C = 8, F = 257, T = 1500;
constexpr int BF  = B * F;                       // 2056
constexpr long long FT  = (long long)F * T;      // 385500
constexpr long long BFT = (long long)B * F * T;  // 3084000
constexpr int T4 = T / 4;                        // 375
constexpr int FT4 = (int)(FT / 4);               // 96375
constexpr int NCH = 32;                          // F-chunks for mask max
constexpr int NT = 192;                          // fused block size

// Scratch (no allocations allowed)
__device__ float g_pmax[2][B][NCH][T];
__device__ float g_recip[2][B][T];

// pair p -> (c,d), c<d, canonical pidx order
__device__ constexpr int PCa[28] = {0,0,0,0,0,0,0, 1,1,1,1,1,1, 2,2,2,2,2, 3,3,3,3, 4,4,4, 5,5, 6};
__device__ constexpr int PDa[28] = {1,2,3,4,5,6,7, 2,3,4,5,6,7, 3,4,5,6,7, 4,5,6,7, 5,6,7, 6,7, 7};

// ---------------------------------------------------------------------------
// Kernel 1a: partial max over F-chunk of |mask| (R15 form: 512 blocks).
// ---------------------------------------------------------------------------
__global__ void mask_max_part(const float* __restrict__ sm,
                              const float* __restrict__ nm) {
    int blk = blockIdx.x;
    int chunk = blk & (NCH - 1), b = (blk >> 5) & 7, m = blk >> 8;
    int i = threadIdx.x;
    if (i >= T4) return;
    // F = 257 = 9 + 31*8
    int fs = chunk ? 9 + (chunk - 1) * 8 : 0;
    int fe = fs + (chunk ? 8 : 9);
    const float4* src = (const float4*)((m ? nm : sm) + (long long)b * FT);
    float4 mx = make_float4(0.f, 0.f, 0.f, 0.f);
    #pragma unroll 4
    for (int f = fs; f < fe; f++) {
        float4 v = src[(long long)f * T4 + i];
        mx.x = fmaxf(mx.x, fabsf(v.x));
        mx.y = fmaxf(mx.y, fabsf(v.y));
        mx.z = fmaxf(mx.z, fabsf(v.z));
        mx.w = fmaxf(mx.w, fabsf(v.w));
    }
    ((float4*)g_pmax[m][b][chunk])[i] = mx;
}

// Kernel 1b: combine NCH partials -> reciprocal.
__global__ void mask_recip_kernel() {
    int blk = blockIdx.x;
    int b = blk & 7, m = blk >> 3;
    int i = threadIdx.x;
    if (i >= T4) return;
    float4 a = ((float4*)g_pmax[m][b][0])[i];
    #pragma unroll
    for (int c = 1; c < NCH; c++) {
        float4 v = ((float4*)g_pmax[m][b][c])[i];
        a.x = fmaxf(a.x, v.x); a.y = fmaxf(a.y, v.y);
        a.z = fmaxf(a.z, v.z); a.w = fmaxf(a.w, v.w);
    }
    float4 r;
    r.x = 1.0f / (a.x + EPS); r.y = 1.0f / (a.y + EPS);
    r.z = 1.0f / (a.z + EPS); r.w = 1.0f / (a.w + EPS);
    ((float4*)g_recip[m][b])[i] = r;
}

// ---------------------------------------------------------------------------
// Fused kernel: two-pass entry-split PSD accumulate -> parallel solve ->
// beamform from smem. One block per (b,f), 192 threads.
// Pass 0: pairs 0..13, diags 0..3, densities (66 acc) + stage tile/msn.
// Pass 1: pairs 14..27, diags 4..7 (64 acc), sweeping the smem tile.
// ---------------------------------------------------------------------------
__device__ __forceinline__ int pidx(int c, int d) {
    return c * 7 - (c * (c - 1)) / 2 + (d - c - 1);
}

template <int PASS>
__device__ __forceinline__ void accum_t(float* acc, const float* xr,
                                        const float* xi, float ms, float mn) {
    #pragma unroll
    for (int j = 0; j < 4; j++) {
        int c = (PASS ? 4 : 0) + j;
        float p = fmaf(xr[c], xr[c], xi[c] * xi[c]);
        acc[56 + 2 * j]     = fmaf(ms, p, acc[56 + 2 * j]);
        acc[56 + 2 * j + 1] = fmaf(mn, p, acc[56 + 2 * j + 1]);
    }
    #pragma unroll
    for (int j = 0; j < 14; j++) {
        int p = (PASS ? 14 : 0) + j;
        int c = PCa[p], d = PDa[p];
        float orr = fmaf(xr[c], xr[d], xi[c] * xi[d]);
        float oii = fmaf(xi[c], xr[d], -xr[c] * xi[d]);
        acc[4 * j + 0] = fmaf(ms, orr, acc[4 * j + 0]);
        acc[4 * j + 1] = fmaf(ms, oii, acc[4 * j + 1]);
        acc[4 * j + 2] = fmaf(mn, orr, acc[4 * j + 2]);
        acc[4 * j + 3] = fmaf(mn, oii, acc[4 * j + 3]);
    }
    if (PASS == 0) { acc[64] += ms; acc[65] += mn; }
}

#define DO_T(PASS, COMP)                                                  \
    {                                                                     \
        float xr[8], xi[8];                                               \
        _Pragma("unroll") for (int c = 0; c < 8; c++) {                   \
            xr[c] = xr4[c].COMP; xi[c] = xi4[c].COMP;                     \
        }                                                                 \
        accum_t<PASS>(acc, xr, xi, msv.COMP, mnv.COMP);                   \
    }

// Warp-shfl reduce NACC values, publish via sh, then map into sacc.
template <int PASS>
__device__ __forceinline__ void reduce_publish(float* acc, float (*sh)[68],
                                               float* sacc, int tid, int lane,
                                               int wid) {
    constexpr int NACC = PASS ? 64 : 66;
    #pragma unroll
    for (int k = 0; k < NACC; k++) {
        float v = acc[k];
        v += __shfl_down_sync(0xffffffffu, v, 16);
        v += __shfl_down_sync(0xffffffffu, v, 8);
        v += __shfl_down_sync(0xffffffffu, v, 4);
        v += __shfl_down_sync(0xffffffffu, v, 2);
        v += __shfl_down_sync(0xffffffffu, v, 1);
        if (lane == 0) sh[wid][k] = v;
    }
    __syncthreads();
    if (tid < NACC) {
        float v = 0.f;
        #pragma unroll
        for (int w = 0; w < 6; w++) v += sh[w][tid];
        int k = tid;
        if (k < 56) {
            int p = (PASS ? 14 : 0) + (k >> 2);
            int r = k & 3;
            int idx = (r < 2) ? (8 + 2 * p + r) : (71 + 2 * p + r);
            sacc[idx] = v;
        } else if (k < 64) {
            int j = k - 56;
            int c = (PASS ? 4 : 0) + (j >> 1);
            sacc[(j & 1) ? 65 + c : c] = v;
        } else {
            sacc[k == 64 ? 64 : 129] = v;
        }
    }
    __syncthreads();
}

__device__ __forceinline__ void getS(const float* a, float invs,
                                     int r, int c, float& re, float& im) {
    const float IM0 = PSD_EPS + EPS;
    if (r == c)      { re = a[r] * invs;                 im = IM0; }
    else if (r < c)  { int p = pidx(r, c);
                       re = a[8 + 2 * p] * invs;         im = a[9 + 2 * p] * invs + IM0; }
    else             { int p = pidx(c, r);
                       re = a[8 + 2 * p] * invs;         im = -a[9 + 2 * p] * invs + IM0; }
}

constexpr int DYN_SMEM = 18 * T * (int)sizeof(float);   // 108000 B

__global__ __launch_bounds__(NT, 2) void mvdr_fused_kernel(
    const float* __restrict__ sm, const float* __restrict__ nm,
    const float* __restrict__ cr, const float* __restrict__ ci,
    float* __restrict__ out) {
    extern __shared__ float tile[];     // rows 0..7 re, rows 8..15 im
    float* msn = tile + 16 * T;         // interleaved (ms,mn) per t
    __shared__ float sh[6][68];
    __shared__ float sacc[130];

    int bf = blockIdx.x;
    int b = bf / F, f = bf % F;
    int tid = threadIdx.x;
    int lane = tid & 31, wid = tid >> 5;

    const float4* cr4 = (const float4*)(cr + (long long)b * C * FT + (long long)f * T);
    const float4* ci4 = (const float4*)(ci + (long long)b * C * FT + (long long)f * T);
    const float4* sm4 = (const float4*)(sm + (long long)b * FT + (long long)f * T);
    const float4* nm4 = (const float4*)(nm + (long long)b * FT + (long long)f * T);
    const float4* rs4 = (const float4*)(g_recip[0][b]);
    const float4* rn4 = (const float4*)(g_recip[1][b]);

    // ---- Pass 0: global sweep, stage tile + mask products, accumulate half ----
    {
        float acc[66];
        #pragma unroll
        for (int k = 0; k < 66; k++) acc[k] = 0.f;
        #pragma unroll 1
        for (int i = tid; i < T4; i += NT) {
            float4 s = sm4[i], n = nm4[i], a = rs4[i], cc = rn4[i];
            float4 msv = make_float4(s.x * a.x, s.y * a.y, s.z * a.z, s.w * a.w);
            float4 mnv = make_float4(n.x * cc.x, n.y * cc.y, n.z * cc.z, n.w * cc.w);
            ((float4*)msn)[2 * i]     = make_float4(msv.x, mnv.x, msv.y, mnv.y);
            ((float4*)msn)[2 * i + 1] = make_float4(msv.z, mnv.z, msv.w, mnv.w);
            float4 xr4[8], xi4[8];
            #pragma unroll
            for (int c = 0; c < 8; c++) {
                xr4[c] = cr4[c * FT4 + i];
                xi4[c] = ci4[c * FT4 + i];
            }
            #pragma unroll
            for (int c = 0; c < 8; c++) {
                ((float4*)(tile + c * T))[i] = xr4[c];
                ((float4*)(tile + (8 + c) * T))[i] = xi4[c];
            }
            DO_T(0, x) DO_T(0, y) DO_T(0, z) DO_T(0, w)
        }
        reduce_publish<0>(acc, sh, sacc, tid, lane, wid);
    }

    // ---- Pass 1: smem sweep, accumulate remaining entries ----
    {
        float acc[64];
        #pragma unroll
        for (int k = 0; k < 64; k++) acc[k] = 0.f;
        #pragma unroll 1
        for (int i = tid; i < T4; i += NT) {
            float4 m01 = ((const float4*)msn)[2 * i];
            float4 m23 = ((const float4*)msn)[2 * i + 1];
            float4 msv = make_float4(m01.x, m01.z, m23.x, m23.z);
            float4 mnv = make_float4(m01.y, m01.w, m23.y, m23.w);
            float4 xr4[8], xi4[8];
            #pragma unroll
            for (int c = 0; c < 8; c++) {
                xr4[c] = ((const float4*)(tile + c * T))[i];
                xi4[c] = ((const float4*)(tile + (8 + c) * T))[i];
            }
            DO_T(1, x) DO_T(1, y) DO_T(1, z) DO_T(1, w)
        }
        reduce_publish<1>(acc, sh, sacc, tid, lane, wid);
    }

    // ---- Phase C: entry-parallel solve (threads 0..63) ----
    __shared__ float rowr[8], rowi[8], colr[8], coli[8];
    __shared__ float sur[8], sui[8], strv[2], tsum[2][2];
    __shared__ float swr[8], swi[8];
    const float* aS = &sacc[0];
    const float* aN = &sacc[65];
    const float IM0 = PSD_EPS + EPS;
    int i8 = tid >> 3, j8 = tid & 7;
    float nr = 0.f, ni = 0.f;

    if (tid < 64) {
        float invd = 1.0f / fmaxf(aN[64], PSD_EPS);
        if (i8 == j8)      { nr = aN[i8] * invd + EPS;  ni = IM0; }
        else if (i8 < j8)  { int p = pidx(i8, j8);
                             nr = aN[8 + 2 * p] * invd; ni = aN[9 + 2 * p] * invd + IM0; }
        else               { int p = pidx(j8, i8);
                             nr = aN[8 + 2 * p] * invd; ni = -aN[9 + 2 * p] * invd + IM0; }
    }

    // Gauss-Jordan, no pivoting (matrix is strongly diagonally dominant)
    #pragma unroll
    for (int k = 0; k < 8; k++) {
        if (tid < 64) {
            if (i8 == k) { rowr[j8] = nr; rowi[j8] = ni; }
            if (j8 == k) { colr[i8] = nr; coli[i8] = ni; }
        }
        __syncthreads();
        if (tid < 64) {
            float pr = rowr[k], pi = rowi[k];
            float s = 1.0f / fmaf(pr, pr, pi * pi);
            float qr = pr * s, qi = -pi * s;
            if (i8 == k) {
                if (j8 == k) { nr = qr; ni = qi; }
                else { float ar = nr, ai = ni;
                       nr = ar * qr - ai * qi; ni = ar * qi + ai * qr; }
            } else {
                float fr = colr[i8], fi = coli[i8];
                float gr = fr * qr - fi * qi, gi = fr * qi + fi * qr;
                if (j8 == k) { nr = -gr; ni = -gi; }
                else {
                    float br = rowr[j8], bi = rowi[j8];
                    nr -= gr * br - gi * bi;
                    ni -= gr * bi + gi * br;
                }
            }
        }
        __syncthreads();
    }

    if (tid < 64) {
        ni += EPS;
        float invs = 1.0f / fmaxf(aS[64], PSD_EPS);
        float sr, si;
        getS(aS, invs, j8, i8, sr, si);
        float tre = nr * sr - ni * si, tim = nr * si + ni * sr;
        getS(aS, invs, j8, 0, sr, si);
        float ue = nr * sr - ni * si, uim = nr * si + ni * sr;
        #pragma unroll
        for (int o = 1; o < 8; o <<= 1) {
            ue  += __shfl_xor_sync(0xffffffffu, ue, o);
            uim += __shfl_xor_sync(0xffffffffu, uim, o);
        }
        if (j8 == 0) { sur[i8] = ue; sui[i8] = uim; }
        #pragma unroll
        for (int o = 16; o >= 1; o >>= 1) {
            tre += __shfl_down_sync(0xffffffffu, tre, o);
            tim += __shfl_down_sync(0xffffffffu, tim, o);
        }
        if (lane == 0) { tsum[wid][0] = tre; tsum[wid][1] = tim; }
    }
    __syncthreads();
    if (tid == 0) {
        strv[0] = EPS + tsum[0][0] + tsum[1][0];
        strv[1] = tsum[0][1] + tsum[1][1];
    }
    __syncthreads();
    if (tid < 8) {
        float trr = strv[0], tri = strv[1];
        float tm = 1.0f / fmaf(trr, trr, tri * tri);
        float ur = sur[tid], ui = sui[tid];
        float wr = (ur * trr + ui * tri) * tm;
        float wi = (ui * trr - ur * tri) * tm;
        swr[tid] = wr;
        swi[tid] = -wi;                           // conj(weight)
    }
    __syncthreads();

    // ---- Phase D: beamform from smem tile, float4 along t ----
    float wr[8], wi[8];
    #pragma unroll
    for (int c = 0; c < 8; c++) { wr[c] = swr[c]; wi[c] = swi[c]; }
    float4* outr = (float4*)(out + (long long)bf * T);
    float4* outi = (float4*)(out + BFT + (long long)bf * T);
    for (int i = tid; i < T4; i += NT) {
        float4 orv = make_float4(0.f, 0.f, 0.f, 0.f);
        float4 oiv = make_float4(0.f, 0.f, 0.f, 0.f);
        #pragma unroll
        for (int c = 0; c < 8; c++) {
            float4 xr = ((const float4*)(tile + c * T))[i];
            float4 xi = ((const float4*)(tile + (8 + c) * T))[i];
            orv.x = fmaf(wr[c], xr.x, fmaf(-wi[c], xi.x, orv.x));
            orv.y = fmaf(wr[c], xr.y, fmaf(-wi[c], xi.y, orv.y));
            orv.z = fmaf(wr[c], xr.z, fmaf(-wi[c], xi.z, orv.z));
            orv.w = fmaf(wr[c], xr.w, fmaf(-wi[c], xi.w, orv.w));
            oiv.x = fmaf(wr[c], xi.x, fmaf(wi[c], xr.x, oiv.x));
            oiv.y = fmaf(wr[c], xi.y, fmaf(wi[c], xr.y, oiv.y));
            oiv.z = fmaf(wr[c], xi.z, fmaf(wi[c], xr.z, oiv.z));
            oiv.w = fmaf(wr[c], xi.w, fmaf(wi[c], xr.w, oiv.w));
        }
        outr[i] = orv;
        outi[i] = oiv;
    }
}

// ---------------------------------------------------------------------------
extern "C" void kernel_launch(void* const* d_in, const int* in_sizes, int n_in,
                              void* d_out, int out_size) {
    const float* sm = (const float*)d_in[0];
    const float* nm = (const float*)d_in[1];
    const float* cr = (const float*)d_in[2];
    const float* ci = (const float*)d_in[3];
    float* out = (float*)d_out;

    cudaFuncSetAttribute(mvdr_fused_kernel,
                         cudaFuncAttributeMaxDynamicSharedMemorySize, DYN_SMEM);

    mask_max_part<<<2 * B * NCH, 384>>>(sm, nm);
    mask_recip_kernel<<<16, 384>>>();
    mvdr_fused_kernel<<<BF, NT, DYN_SMEM>>>(sm, nm, cr, ci, out);
}